// round 1
// baseline (speedup 1.0000x reference)
#include <cuda_runtime.h>
#include <cuda_bf16.h>
#include <math.h>

// Problem constants (fixed by the reference: B=4, T=2048, C=1024)
#define BB 4
#define TT 2048
#define CC 1024

// -------- Scratch (allocation-free rule: __device__ globals) --------
static __device__ float g_Q[BB * TT * CC];        // 33.5 MB
static __device__ float g_K[BB * TT * CC];        // 33.5 MB
static __device__ float g_V[BB * TT * CC];        // 33.5 MB
static __device__ float g_S[(size_t)BB * TT * TT];// 67 MB (scores, then probs in-place)
static __device__ float g_O[BB * TT * CC];        // 33.5 MB

// ----------------------------------------------------------------------------
// Tiled fp32 GEMM: 128x128 block tile, BK=16, 256 threads, 8x8 per thread.
// MODE 0: C = alpha * A[M,K] @ B[K,N]                      (row-major both)
// MODE 1: C = alpha * A[M,K] @ Bt[N,K]^T  with causal tile skip (bx > by -> skip)
// MODE 2: C = alpha * A[M,K] @ B[K,N]    with k-limit  kEnd = (by+1)*128
// blockIdx.z = batch; per-batch element strides sA, sB, sC.
// All dims here are multiples of 128 (M,N) and 16 (K) -> no bounds checks.
// ----------------------------------------------------------------------------
template <int MODE>
__global__ __launch_bounds__(256)
void gemm128(const float* __restrict__ A, const float* __restrict__ B,
             float* __restrict__ C, int M, int N, int K,
             size_t sA, size_t sB, size_t sC, float alpha)
{
    const int bx = blockIdx.x, by = blockIdx.y, bz = blockIdx.z;
    if (MODE == 1 && bx > by) return;   // tile fully above causal diagonal

    const int m0 = by * 128;
    const int n0 = bx * 128;

    const float* Ab = A + (size_t)bz * sA;
    const float* Bb = B + (size_t)bz * sB;
    float*       Cb = C + (size_t)bz * sC;

    __shared__ float As[16][132];
    __shared__ float Bs[16][132];

    const int tid = threadIdx.x;
    const int tx = tid & 15;         // 0..15
    const int ty = tid >> 4;         // 0..15
    const int tx8 = tx * 8;
    const int ty8 = ty * 8;

    // A-tile loader (also B-tile loader in MODE 1): 128 rows x 16 cols
    const int lr = tid >> 2;          // 0..63
    const int lc = (tid & 3) << 2;    // 0,4,8,12
    // B-tile loader (MODE 0/2): 16 rows x 128 cols
    const int br = tid >> 5;          // 0..7
    const int bc = (tid & 31) << 2;   // 0..124

    float acc[8][8];
    #pragma unroll
    for (int i = 0; i < 8; i++)
        #pragma unroll
        for (int j = 0; j < 8; j++) acc[i][j] = 0.0f;

    const int kEnd = (MODE == 2) ? ((by + 1) * 128 < K ? (by + 1) * 128 : K) : K;

    for (int k0 = 0; k0 < kEnd; k0 += 16) {
        // ---- load A tile (transposed into As[k][m]) ----
        {
            float4 a0 = *(const float4*)(Ab + (size_t)(m0 + lr) * K + k0 + lc);
            float4 a1 = *(const float4*)(Ab + (size_t)(m0 + lr + 64) * K + k0 + lc);
            As[lc + 0][lr] = a0.x; As[lc + 1][lr] = a0.y;
            As[lc + 2][lr] = a0.z; As[lc + 3][lr] = a0.w;
            As[lc + 0][lr + 64] = a1.x; As[lc + 1][lr + 64] = a1.y;
            As[lc + 2][lr + 64] = a1.z; As[lc + 3][lr + 64] = a1.w;
        }
        // ---- load B tile ----
        if (MODE == 1) {
            // B is [N,K] row-major; Bs[k][n] = B[n][k]
            float4 b0 = *(const float4*)(Bb + (size_t)(n0 + lr) * K + k0 + lc);
            float4 b1 = *(const float4*)(Bb + (size_t)(n0 + lr + 64) * K + k0 + lc);
            Bs[lc + 0][lr] = b0.x; Bs[lc + 1][lr] = b0.y;
            Bs[lc + 2][lr] = b0.z; Bs[lc + 3][lr] = b0.w;
            Bs[lc + 0][lr + 64] = b1.x; Bs[lc + 1][lr + 64] = b1.y;
            Bs[lc + 2][lr + 64] = b1.z; Bs[lc + 3][lr + 64] = b1.w;
        } else {
            // B is [K,N] row-major; direct copy
            float4 b0 = *(const float4*)(Bb + (size_t)(k0 + br) * N + n0 + bc);
            float4 b1 = *(const float4*)(Bb + (size_t)(k0 + br + 8) * N + n0 + bc);
            *(float4*)&Bs[br][bc]     = b0;
            *(float4*)&Bs[br + 8][bc] = b1;
        }
        __syncthreads();

        #pragma unroll
        for (int kk = 0; kk < 16; kk++) {
            float4 xa0 = *(const float4*)&As[kk][ty8];
            float4 xa1 = *(const float4*)&As[kk][ty8 + 4];
            float4 yb0 = *(const float4*)&Bs[kk][tx8];
            float4 yb1 = *(const float4*)&Bs[kk][tx8 + 4];
            float a[8] = {xa0.x, xa0.y, xa0.z, xa0.w, xa1.x, xa1.y, xa1.z, xa1.w};
            float b[8] = {yb0.x, yb0.y, yb0.z, yb0.w, yb1.x, yb1.y, yb1.z, yb1.w};
            #pragma unroll
            for (int i = 0; i < 8; i++)
                #pragma unroll
                for (int j = 0; j < 8; j++)
                    acc[i][j] = fmaf(a[i], b[j], acc[i][j]);
        }
        __syncthreads();
    }

    // ---- epilogue ----
    #pragma unroll
    for (int i = 0; i < 8; i++) {
        float* crow = Cb + (size_t)(m0 + ty8 + i) * N + n0 + tx8;
        float4 o0, o1;
        o0.x = acc[i][0] * alpha; o0.y = acc[i][1] * alpha;
        o0.z = acc[i][2] * alpha; o0.w = acc[i][3] * alpha;
        o1.x = acc[i][4] * alpha; o1.y = acc[i][5] * alpha;
        o1.z = acc[i][6] * alpha; o1.w = acc[i][7] * alpha;
        *(float4*)(crow)     = o0;
        *(float4*)(crow + 4) = o1;
    }
}

// ----------------------------------------------------------------------------
// Causal softmax over rows of S[b][t][:], length t+1; zero-fills s>t so the
// following P@V GEMM needs no masking beyond its k-limit.
// grid = B*T blocks, 256 threads.
// ----------------------------------------------------------------------------
__global__ __launch_bounds__(256)
void softmax_causal(float* __restrict__ S)
{
    const int r = blockIdx.x;            // 0 .. B*T-1
    const int t = r & (TT - 1);
    float* row = S + (size_t)r * TT;
    const int len = t + 1;

    const int tid = threadIdx.x;
    const int lane = tid & 31, wid = tid >> 5;
    __shared__ float red[32];

    // pass 1: max
    float m = -3.0e38f;
    for (int s = tid; s < len; s += 256) m = fmaxf(m, row[s]);
    #pragma unroll
    for (int o = 16; o > 0; o >>= 1) m = fmaxf(m, __shfl_xor_sync(0xffffffffu, m, o));
    if (lane == 0) red[wid] = m;
    __syncthreads();
    if (tid < 32) {
        float v = (tid < 8) ? red[tid] : -3.0e38f;
        #pragma unroll
        for (int o = 4; o > 0; o >>= 1) v = fmaxf(v, __shfl_xor_sync(0xffffffffu, v, o));
        if (tid == 0) red[0] = v;
    }
    __syncthreads();
    m = red[0];
    __syncthreads();

    // pass 2: exp + sum (store exp in-place)
    float sum = 0.0f;
    for (int s = tid; s < len; s += 256) {
        float e = expf(row[s] - m);
        row[s] = e;
        sum += e;
    }
    #pragma unroll
    for (int o = 16; o > 0; o >>= 1) sum += __shfl_xor_sync(0xffffffffu, sum, o);
    if (lane == 0) red[wid] = sum;
    __syncthreads();
    if (tid < 32) {
        float v = (tid < 8) ? red[tid] : 0.0f;
        #pragma unroll
        for (int o = 4; o > 0; o >>= 1) v += __shfl_xor_sync(0xffffffffu, v, o);
        if (tid == 0) red[0] = v;
    }
    __syncthreads();
    const float inv = 1.0f / red[0];

    // pass 3: normalize valid region, zero the masked region
    for (int s = tid; s < len; s += 256) row[s] *= inv;
    for (int s = len + tid; s < TT; s += 256) row[s] = 0.0f;
}

// ----------------------------------------------------------------------------
// Launch
// ----------------------------------------------------------------------------
extern "C" void kernel_launch(void* const* d_in, const int* in_sizes, int n_in,
                              void* d_out, int out_size)
{
    const float* X  = (const float*)d_in[0];
    const float* Wq = (const float*)d_in[1];
    const float* Wk = (const float*)d_in[2];
    const float* Wv = (const float*)d_in[3];
    const float* Wo = (const float*)d_in[4];
    float* out = (float*)d_out;

    float *Q, *K, *V, *S, *O;
    cudaGetSymbolAddress((void**)&Q, g_Q);
    cudaGetSymbolAddress((void**)&K, g_K);
    cudaGetSymbolAddress((void**)&V, g_V);
    cudaGetSymbolAddress((void**)&S, g_S);
    cudaGetSymbolAddress((void**)&O, g_O);

    const int M  = BB * TT;      // 8192
    const float scale = 1.0f / 32.0f;   // 1/sqrt(1024)

    // 1) QKV projections: [8192,1024] @ [1024,1024]
    {
        dim3 grid(CC / 128, M / 128, 1);
        gemm128<0><<<grid, 256>>>(X, Wq, Q, M, CC, CC, 0, 0, 0, 1.0f);
        gemm128<0><<<grid, 256>>>(X, Wk, K, M, CC, CC, 0, 0, 0, 1.0f);
        gemm128<0><<<grid, 256>>>(X, Wv, V, M, CC, CC, 0, 0, 0, 1.0f);
    }

    // 2) Scores: S[b] = scale * Q[b] @ K[b]^T (causal tile-skip)
    {
        dim3 grid(TT / 128, TT / 128, BB);
        gemm128<1><<<grid, 256>>>(Q, K, S, TT, TT, CC,
                                  (size_t)TT * CC, (size_t)TT * CC,
                                  (size_t)TT * TT, scale);
    }

    // 3) Causal softmax (in-place, zero-fills masked region)
    softmax_causal<<<BB * TT, 256>>>(S);

    // 4) O[b] = P[b] @ V[b]  (k-limited by causal structure)
    {
        dim3 grid(CC / 128, TT / 128, BB);
        gemm128<2><<<grid, 256>>>(S, V, O, TT, CC, TT,
                                  (size_t)TT * TT, (size_t)TT * CC,
                                  (size_t)TT * CC, 1.0f);
    }

    // 5) out = O @ Wo
    {
        dim3 grid(CC / 128, M / 128, 1);
        gemm128<0><<<grid, 256>>>(O, Wo, out, M, CC, CC, 0, 0, 0, 1.0f);
    }
}

// round 3
// speedup vs baseline: 3.9482x; 3.9482x over previous
#include <cuda_runtime.h>
#include <cuda_bf16.h>
#include <stdint.h>
#include <math.h>

#define BB 4
#define TT 2048
#define CC 1024
#define MT (BB*TT)   // 8192

typedef __nv_bfloat16 bf16;

// ---------------- Scratch (__device__ globals; no allocation) ----------------
static __device__ bf16 g_Xh[MT*CC], g_Xl[MT*CC];
static __device__ bf16 g_Wqh[CC*CC], g_Wql[CC*CC];
static __device__ bf16 g_Wkh[CC*CC], g_Wkl[CC*CC];
static __device__ bf16 g_Wvh[CC*CC], g_Wvl[CC*CC];
static __device__ bf16 g_Woh[CC*CC], g_Wol[CC*CC];
static __device__ bf16 g_Qh[MT*CC], g_Ql[MT*CC];
static __device__ bf16 g_Kh[MT*CC], g_Kl[MT*CC];
static __device__ bf16 g_Vth[MT*CC], g_Vtl[MT*CC];   // [b][c][t] transposed V
static __device__ float g_S[(size_t)BB*TT*TT];
static __device__ bf16 g_Ph[(size_t)BB*TT*TT], g_Pl[(size_t)BB*TT*TT];
static __device__ bf16 g_Oh[MT*CC], g_Ol[MT*CC];

// ---------------- helpers ----------------
__device__ __forceinline__ uint32_t smem_u32(const void* p) {
    uint32_t a;
    asm("{ .reg .u64 t; cvta.to.shared.u64 t, %1; cvt.u32.u64 %0, t; }" : "=r"(a) : "l"(p));
    return a;
}
#define CP16(s, g) asm volatile("cp.async.cg.shared.global [%0], [%1], 16;" :: "r"(s), "l"(g) : "memory")
#define CPCOMMIT()  asm volatile("cp.async.commit_group;" ::: "memory")
#define CPWAIT1()   asm volatile("cp.async.wait_group 1;" ::: "memory")
#define LDSM4(r0,r1,r2,r3,a) \
    asm volatile("ldmatrix.sync.aligned.m8n8.x4.shared.b16 {%0,%1,%2,%3}, [%4];" \
                 : "=r"(r0),"=r"(r1),"=r"(r2),"=r"(r3) : "r"(a))

__device__ __forceinline__ void mma16816(float* c, const uint32_t* a, uint32_t b0, uint32_t b1) {
    asm volatile(
        "mma.sync.aligned.m16n8k16.row.col.f32.bf16.bf16.f32 "
        "{%0,%1,%2,%3}, {%4,%5,%6,%7}, {%8,%9}, {%0,%1,%2,%3};"
        : "+f"(c[0]), "+f"(c[1]), "+f"(c[2]), "+f"(c[3])
        : "r"(a[0]), "r"(a[1]), "r"(a[2]), "r"(a[3]), "r"(b0), "r"(b1));
}

__device__ __forceinline__ void split2(float x, bf16& h, bf16& l) {
    h = __float2bfloat16(x);
    l = __float2bfloat16(x - __bfloat162float(h));
}

// swizzled byte offset inside a 128x32 bf16 tile (64B rows)
__device__ __forceinline__ uint32_t swz(int row, int kbyte) {
    return (uint32_t)(row * 64 + (kbyte ^ ((row & 6) << 3)));
}

// ---------------- GEMM: D = A @ B^T, A[M,K],B[N,K] bf16 hi/lo, 3-term ----------------
// Tile 128x128x32, 8 warps (warp 32x64), 3-stage cp.async pipeline.
// MODE 0: epi fp32*alpha
// MODE 1: epi bf16 hi/lo
// MODE 2: epi bf16 hi/lo transposed per-batch (V -> Vt[b][c][t])
// MODE 3: causal tile-skip (bx>by) + epi fp32*alpha
// MODE 4: k-limit kEnd=(by+1)*128 + epi bf16 hi/lo
static constexpr int BK = 32;
static constexpr int TILE_B = 128 * BK * 2;          // 8 KB per term tile
static constexpr int OFF_AH = 0, OFF_AL = TILE_B, OFF_BH = 2*TILE_B, OFF_BL = 3*TILE_B;
static constexpr int STAGE_B = 4 * TILE_B;           // 32 KB
static constexpr int STAGES = 3;
static constexpr int SMEM_DYN = STAGES * STAGE_B;    // 96 KB

template <int MODE>
__global__ __launch_bounds__(256, 2)
void gemm_mma(const bf16* __restrict__ Ah, const bf16* __restrict__ Al,
              const bf16* __restrict__ Bh, const bf16* __restrict__ Bl,
              float* __restrict__ Cf, bf16* __restrict__ Ch, bf16* __restrict__ Cl,
              int lda, int ldb, int kmax, int Nc,
              size_t sA, size_t sB, size_t sC, float alpha)
{
    const int bx = blockIdx.x, by = blockIdx.y, bz = blockIdx.z;
    if (MODE == 3 && bx > by) return;
    const int m0 = by * 128, n0 = bx * 128;
    if (MODE == 4) kmax = (by + 1) * 128;
    const int nit = kmax / BK;

    extern __shared__ char dsm[];
    const uint32_t sbase = smem_u32(dsm);

    const int tid = threadIdx.x;
    const int wid = tid >> 5, lane = tid & 31;
    const int wm = wid & 3, wn = wid >> 2;       // warp tile: rows wm*32, cols wn*64

    const bf16* pAh = Ah + bz * sA;
    const bf16* pAl = Al + bz * sA;
    const bf16* pBh = Bh + bz * sB;
    const bf16* pBl = Bl + bz * sB;

    // --- per-thread loader mapping: 2 chunks of 16B per term-tile ---
    const int ch0 = tid, ch1 = tid + 256;
    const int r0c = ch0 >> 2, k0c = (ch0 & 3) << 4;   // row, kbyte
    const int r1c = ch1 >> 2, k1c = (ch1 & 3) << 4;
    const uint32_t so0 = swz(r0c, k0c), so1 = swz(r1c, k1c);

    // --- per-thread ldmatrix offsets (relative to term-tile base) ---
    const int lr = lane & 15, lc16 = (lane >> 4) << 4;  // row-in-16, kbyte chunk
    uint32_t aoff[2][2], boff[4][2];
    #pragma unroll
    for (int mi = 0; mi < 2; mi++) {
        int row = wm * 32 + mi * 16 + lr;
        #pragma unroll
        for (int ks = 0; ks < 2; ks++)
            aoff[mi][ks] = swz(row, ks * 32 + lc16);
    }
    #pragma unroll
    for (int nb = 0; nb < 4; nb++) {
        int row = wn * 64 + nb * 16 + lr;
        #pragma unroll
        for (int ks = 0; ks < 2; ks++)
            boff[nb][ks] = swz(row, ks * 32 + lc16);
    }

    float acc[2][8][4];
    #pragma unroll
    for (int mi = 0; mi < 2; mi++)
        #pragma unroll
        for (int nf = 0; nf < 8; nf++)
            #pragma unroll
            for (int q = 0; q < 4; q++) acc[mi][nf][q] = 0.0f;

    auto prefetch = [&](int it, int stage) {
        const int k0 = it * BK;
        const uint32_t sb = sbase + stage * STAGE_B;
        const bf16* a0 = pAh + (size_t)(m0 + r0c) * lda + k0 + (k0c >> 1);
        const bf16* a1 = pAh + (size_t)(m0 + r1c) * lda + k0 + (k1c >> 1);
        const bf16* al0 = pAl + (size_t)(m0 + r0c) * lda + k0 + (k0c >> 1);
        const bf16* al1 = pAl + (size_t)(m0 + r1c) * lda + k0 + (k1c >> 1);
        const bf16* b0 = pBh + (size_t)(n0 + r0c) * ldb + k0 + (k0c >> 1);
        const bf16* b1 = pBh + (size_t)(n0 + r1c) * ldb + k0 + (k1c >> 1);
        const bf16* bl0 = pBl + (size_t)(n0 + r0c) * ldb + k0 + (k0c >> 1);
        const bf16* bl1 = pBl + (size_t)(n0 + r1c) * ldb + k0 + (k1c >> 1);
        CP16(sb + OFF_AH + so0, a0);  CP16(sb + OFF_AH + so1, a1);
        CP16(sb + OFF_AL + so0, al0); CP16(sb + OFF_AL + so1, al1);
        CP16(sb + OFF_BH + so0, b0);  CP16(sb + OFF_BH + so1, b1);
        CP16(sb + OFF_BL + so0, bl0); CP16(sb + OFF_BL + so1, bl1);
    };

    prefetch(0, 0); CPCOMMIT();
    if (nit > 1) prefetch(1, 1);
    CPCOMMIT();

    for (int it = 0; it < nit; it++) {
        CPWAIT1();
        __syncthreads();
        if (it + 2 < nit) prefetch(it + 2, (it + 2) % STAGES);
        CPCOMMIT();

        const uint32_t sb = sbase + (it % STAGES) * STAGE_B;
        #pragma unroll
        for (int ks = 0; ks < 2; ks++) {
            uint32_t Afr[2][4], Bt[4][4];
            #pragma unroll
            for (int mi = 0; mi < 2; mi++)
                LDSM4(Afr[mi][0], Afr[mi][1], Afr[mi][2], Afr[mi][3],
                      sb + OFF_AH + aoff[mi][ks]);
            #pragma unroll
            for (int nb = 0; nb < 4; nb++)
                LDSM4(Bt[nb][0], Bt[nb][1], Bt[nb][2], Bt[nb][3],
                      sb + OFF_BH + boff[nb][ks]);
            // hi * hi
            #pragma unroll
            for (int mi = 0; mi < 2; mi++)
                #pragma unroll
                for (int nf = 0; nf < 8; nf++)
                    mma16816(acc[mi][nf], Afr[mi], Bt[nf >> 1][nf & 1], Bt[nf >> 1][(nf & 1) + 2]);
            // lo * hi
            {
                uint32_t Alf[2][4];
                #pragma unroll
                for (int mi = 0; mi < 2; mi++)
                    LDSM4(Alf[mi][0], Alf[mi][1], Alf[mi][2], Alf[mi][3],
                          sb + OFF_AL + aoff[mi][ks]);
                #pragma unroll
                for (int mi = 0; mi < 2; mi++)
                    #pragma unroll
                    for (int nf = 0; nf < 8; nf++)
                        mma16816(acc[mi][nf], Alf[mi], Bt[nf >> 1][nf & 1], Bt[nf >> 1][(nf & 1) + 2]);
            }
            // hi * lo  (overwrite Bt with B-lo)
            #pragma unroll
            for (int nb = 0; nb < 4; nb++)
                LDSM4(Bt[nb][0], Bt[nb][1], Bt[nb][2], Bt[nb][3],
                      sb + OFF_BL + boff[nb][ks]);
            #pragma unroll
            for (int mi = 0; mi < 2; mi++)
                #pragma unroll
                for (int nf = 0; nf < 8; nf++)
                    mma16816(acc[mi][nf], Afr[mi], Bt[nf >> 1][nf & 1], Bt[nf >> 1][(nf & 1) + 2]);
        }
    }

    // ---------------- epilogue ----------------
    const int quad = lane >> 2, tq = lane & 3;
    #pragma unroll
    for (int mi = 0; mi < 2; mi++) {
        #pragma unroll
        for (int h = 0; h < 2; h++) {           // row half (m, m+8)
            const int r = m0 + wm * 32 + mi * 16 + quad + h * 8;
            if (MODE == 0 || MODE == 3) {
                float* crow = Cf + bz * sC + (size_t)r * Nc + n0 + wn * 64 + tq * 2;
                #pragma unroll
                for (int nf = 0; nf < 8; nf++) {
                    float2 v;
                    v.x = acc[mi][nf][h * 2 + 0] * alpha;
                    v.y = acc[mi][nf][h * 2 + 1] * alpha;
                    *(float2*)(crow + nf * 8) = v;
                }
            } else if (MODE == 1 || MODE == 4) {
                bf16* hrow = Ch + bz * sC + (size_t)r * Nc + n0 + wn * 64 + tq * 2;
                bf16* lrow = Cl + bz * sC + (size_t)r * Nc + n0 + wn * 64 + tq * 2;
                #pragma unroll
                for (int nf = 0; nf < 8; nf++) {
                    bf16 h0, l0, h1, l1;
                    split2(acc[mi][nf][h * 2 + 0], h0, l0);
                    split2(acc[mi][nf][h * 2 + 1], h1, l1);
                    __nv_bfloat162 hp; hp.x = h0; hp.y = h1;
                    __nv_bfloat162 lp; lp.x = l0; lp.y = l1;
                    *(__nv_bfloat162*)(hrow + nf * 8) = hp;
                    *(__nv_bfloat162*)(lrow + nf * 8) = lp;
                }
            } else {  // MODE 2: Vt[b][c][t]
                const int b = r >> 11, t = r & (TT - 1);
                const size_t base = (size_t)b * CC * TT + t;
                #pragma unroll
                for (int nf = 0; nf < 8; nf++) {
                    const int c0 = n0 + wn * 64 + nf * 8 + tq * 2;
                    bf16 h0, l0, h1, l1;
                    split2(acc[mi][nf][h * 2 + 0], h0, l0);
                    split2(acc[mi][nf][h * 2 + 1], h1, l1);
                    Ch[base + (size_t)c0 * TT] = h0;
                    Cl[base + (size_t)c0 * TT] = l0;
                    Ch[base + (size_t)(c0 + 1) * TT] = h1;
                    Cl[base + (size_t)(c0 + 1) * TT] = l1;
                }
            }
        }
    }
}

// ---------------- fp32 -> bf16 hi/lo split ----------------
__global__ __launch_bounds__(256)
void split_f32(const float* __restrict__ x, bf16* __restrict__ h, bf16* __restrict__ l, int n)
{
    int i = (blockIdx.x * 256 + threadIdx.x) * 4;
    if (i >= n) return;
    float4 v = *(const float4*)(x + i);
    __align__(8) bf16 hh[4], ll[4];
    split2(v.x, hh[0], ll[0]); split2(v.y, hh[1], ll[1]);
    split2(v.z, hh[2], ll[2]); split2(v.w, hh[3], ll[3]);
    *(uint2*)(h + i) = *(uint2*)hh;
    *(uint2*)(l + i) = *(uint2*)ll;
}

// W[k][n] -> Wt hi/lo [n][k]
__global__ __launch_bounds__(256)
void wsplitT(const float* __restrict__ W, bf16* __restrict__ Th, bf16* __restrict__ Tl)
{
    __shared__ float t[32][33];
    const int n0 = blockIdx.x * 32, k0 = blockIdx.y * 32;
    const int tx = threadIdx.x & 31, ty = threadIdx.x >> 5;
    #pragma unroll
    for (int i = 0; i < 4; i++)
        t[ty + 8*i][tx] = W[(size_t)(k0 + ty + 8*i) * CC + n0 + tx];
    __syncthreads();
    #pragma unroll
    for (int i = 0; i < 4; i++) {
        float v = t[tx][ty + 8*i];
        bf16 h, l;
        split2(v, h, l);
        Th[(size_t)(n0 + ty + 8*i) * CC + k0 + tx] = h;
        Tl[(size_t)(n0 + ty + 8*i) * CC + k0 + tx] = l;
    }
}

// ---------------- causal softmax: fp32 row -> bf16 hi/lo probs ----------------
__global__ __launch_bounds__(256)
void softmax_causal(float* __restrict__ S, bf16* __restrict__ Ph, bf16* __restrict__ Pl)
{
    const int r = blockIdx.x;
    const int t = r & (TT - 1);
    float* row = S + (size_t)r * TT;
    bf16* ph = Ph + (size_t)r * TT;
    bf16* pl = Pl + (size_t)r * TT;
    const int len = t + 1;
    const int zmax = ((t >> 7) + 1) << 7;

    const int tid = threadIdx.x, lane = tid & 31, wid = tid >> 5;
    __shared__ float red[32];

    float m = -3.0e38f;
    for (int s = tid; s < len; s += 256) m = fmaxf(m, row[s]);
    #pragma unroll
    for (int o = 16; o > 0; o >>= 1) m = fmaxf(m, __shfl_xor_sync(0xffffffffu, m, o));
    if (lane == 0) red[wid] = m;
    __syncthreads();
    if (tid < 32) {
        float v = (tid < 8) ? red[tid] : -3.0e38f;
        #pragma unroll
        for (int o = 4; o > 0; o >>= 1) v = fmaxf(v, __shfl_xor_sync(0xffffffffu, v, o));
        if (tid == 0) red[0] = v;
    }
    __syncthreads();
    m = red[0];
    __syncthreads();

    float sum = 0.0f;
    for (int s = tid; s < len; s += 256) {
        float e = expf(row[s] - m);
        row[s] = e;
        sum += e;
    }
    #pragma unroll
    for (int o = 16; o > 0; o >>= 1) sum += __shfl_xor_sync(0xffffffffu, sum, o);
    if (lane == 0) red[wid] = sum;
    __syncthreads();
    if (tid < 32) {
        float v = (tid < 8) ? red[tid] : 0.0f;
        #pragma unroll
        for (int o = 4; o > 0; o >>= 1) v += __shfl_xor_sync(0xffffffffu, v, o);
        if (tid == 0) red[0] = v;
    }
    __syncthreads();
    const float inv = 1.0f / red[0];

    const bf16 z = __float2bfloat16(0.0f);
    for (int s = tid; s < len; s += 256) {
        float p = row[s] * inv;
        bf16 h, l;
        split2(p, h, l);
        ph[s] = h; pl[s] = l;
    }
    for (int s = len + tid; s < zmax; s += 256) { ph[s] = z; pl[s] = z; }
}

// ---------------- launch ----------------
extern "C" void kernel_launch(void* const* d_in, const int* in_sizes, int n_in,
                              void* d_out, int out_size)
{
    const float* X  = (const float*)d_in[0];
    const float* Wq = (const float*)d_in[1];
    const float* Wk = (const float*)d_in[2];
    const float* Wv = (const float*)d_in[3];
    const float* Wo = (const float*)d_in[4];
    float* out = (float*)d_out;

    bf16 *Xh,*Xl,*Wqh,*Wql,*Wkh,*Wkl,*Wvh,*Wvl,*Woh,*Wol;
    bf16 *Qh,*Ql,*Kh,*Kl,*Vth,*Vtl,*Ph,*Pl,*Oh,*Ol;
    float* S;
    cudaGetSymbolAddress((void**)&Xh, g_Xh);   cudaGetSymbolAddress((void**)&Xl, g_Xl);
    cudaGetSymbolAddress((void**)&Wqh, g_Wqh); cudaGetSymbolAddress((void**)&Wql, g_Wql);
    cudaGetSymbolAddress((void**)&Wkh, g_Wkh); cudaGetSymbolAddress((void**)&Wkl, g_Wkl);
    cudaGetSymbolAddress((void**)&Wvh, g_Wvh); cudaGetSymbolAddress((void**)&Wvl, g_Wvl);
    cudaGetSymbolAddress((void**)&Woh, g_Woh); cudaGetSymbolAddress((void**)&Wol, g_Wol);
    cudaGetSymbolAddress((void**)&Qh, g_Qh);   cudaGetSymbolAddress((void**)&Ql, g_Ql);
    cudaGetSymbolAddress((void**)&Kh, g_Kh);   cudaGetSymbolAddress((void**)&Kl, g_Kl);
    cudaGetSymbolAddress((void**)&Vth, g_Vth); cudaGetSymbolAddress((void**)&Vtl, g_Vtl);
    cudaGetSymbolAddress((void**)&Ph, g_Ph);   cudaGetSymbolAddress((void**)&Pl, g_Pl);
    cudaGetSymbolAddress((void**)&Oh, g_Oh);   cudaGetSymbolAddress((void**)&Ol, g_Ol);
    cudaGetSymbolAddress((void**)&S, g_S);

    cudaFuncSetAttribute(gemm_mma<0>, cudaFuncAttributeMaxDynamicSharedMemorySize, SMEM_DYN);
    cudaFuncSetAttribute(gemm_mma<1>, cudaFuncAttributeMaxDynamicSharedMemorySize, SMEM_DYN);
    cudaFuncSetAttribute(gemm_mma<2>, cudaFuncAttributeMaxDynamicSharedMemorySize, SMEM_DYN);
    cudaFuncSetAttribute(gemm_mma<3>, cudaFuncAttributeMaxDynamicSharedMemorySize, SMEM_DYN);
    cudaFuncSetAttribute(gemm_mma<4>, cudaFuncAttributeMaxDynamicSharedMemorySize, SMEM_DYN);

    // 0) splits
    split_f32<<<MT*CC/1024, 256>>>(X, Xh, Xl, MT*CC);
    wsplitT<<<dim3(32,32), 256>>>(Wq, Wqh, Wql);
    wsplitT<<<dim3(32,32), 256>>>(Wk, Wkh, Wkl);
    wsplitT<<<dim3(32,32), 256>>>(Wv, Wvh, Wvl);
    wsplitT<<<dim3(32,32), 256>>>(Wo, Woh, Wol);

    // 1) QKV projections
    gemm_mma<1><<<dim3(8,64,1), 256, SMEM_DYN>>>(Xh, Xl, Wqh, Wql, nullptr, Qh, Ql,
                                                 CC, CC, CC, CC, 0, 0, 0, 1.0f);
    gemm_mma<1><<<dim3(8,64,1), 256, SMEM_DYN>>>(Xh, Xl, Wkh, Wkl, nullptr, Kh, Kl,
                                                 CC, CC, CC, CC, 0, 0, 0, 1.0f);
    gemm_mma<2><<<dim3(8,64,1), 256, SMEM_DYN>>>(Xh, Xl, Wvh, Wvl, nullptr, Vth, Vtl,
                                                 CC, CC, CC, CC, 0, 0, 0, 1.0f);

    // 2) scores: S[b] = (Q @ K^T)/32 with causal tile-skip
    gemm_mma<3><<<dim3(16,16,4), 256, SMEM_DYN>>>(Qh, Ql, Kh, Kl, S, nullptr, nullptr,
                                                  CC, CC, CC, TT,
                                                  (size_t)TT*CC, (size_t)TT*CC, (size_t)TT*TT,
                                                  1.0f/32.0f);

    // 3) softmax -> P hi/lo
    softmax_causal<<<BB*TT, 256>>>(S, Ph, Pl);

    // 4) O = P @ Vt^T (k-limited)
    gemm_mma<4><<<dim3(8,16,4), 256, SMEM_DYN>>>(Ph, Pl, Vth, Vtl, nullptr, Oh, Ol,
                                                 TT, TT, TT, CC,
                                                 (size_t)TT*TT, (size_t)CC*TT, (size_t)TT*CC,
                                                 1.0f);

    // 5) out = O @ Wo^T
    gemm_mma<0><<<dim3(8,64,1), 256, SMEM_DYN>>>(Oh, Ol, Woh, Wol, out, nullptr, nullptr,
                                                 CC, CC, CC, CC, 0, 0, 0, 1.0f);
}

// round 4
// speedup vs baseline: 4.5406x; 1.1500x over previous
#include <cuda_runtime.h>
#include <cuda_bf16.h>
#include <stdint.h>
#include <math.h>

#define BB 4
#define TT 2048
#define CC 1024
#define MT (BB*TT)   // 8192

typedef __nv_bfloat16 bf16;

// ---------------- Scratch (__device__ globals; no allocation) ----------------
static __device__ bf16 g_Xh[MT*CC], g_Xl[MT*CC];
static __device__ bf16 g_Wqh[CC*CC], g_Wql[CC*CC];
static __device__ bf16 g_Wkh[CC*CC], g_Wkl[CC*CC];
static __device__ bf16 g_Wvh[CC*CC], g_Wvl[CC*CC];
static __device__ bf16 g_Woh[CC*CC], g_Wol[CC*CC];
static __device__ bf16 g_Qh[MT*CC], g_Ql[MT*CC];
static __device__ bf16 g_Kh[MT*CC], g_Kl[MT*CC];
static __device__ bf16 g_Vth[MT*CC], g_Vtl[MT*CC];   // [b][c][t] transposed V
static __device__ float g_S[(size_t)BB*TT*TT];
static __device__ bf16 g_Ph[(size_t)BB*TT*TT], g_Pl[(size_t)BB*TT*TT];
static __device__ bf16 g_Oh[MT*CC], g_Ol[MT*CC];

// ---------------- helpers ----------------
__device__ __forceinline__ uint32_t smem_u32(const void* p) {
    uint32_t a;
    asm("{ .reg .u64 t; cvta.to.shared.u64 t, %1; cvt.u32.u64 %0, t; }" : "=r"(a) : "l"(p));
    return a;
}
#define CP16(s, g) asm volatile("cp.async.cg.shared.global [%0], [%1], 16;" :: "r"(s), "l"(g) : "memory")
#define CPCOMMIT()  asm volatile("cp.async.commit_group;" ::: "memory")
#define CPWAIT1()   asm volatile("cp.async.wait_group 1;" ::: "memory")
#define LDSM4(r0,r1,r2,r3,a) \
    asm volatile("ldmatrix.sync.aligned.m8n8.x4.shared.b16 {%0,%1,%2,%3}, [%4];" \
                 : "=r"(r0),"=r"(r1),"=r"(r2),"=r"(r3) : "r"(a))

__device__ __forceinline__ void mma16816(float* c, const uint32_t* a, uint32_t b0, uint32_t b1) {
    asm volatile(
        "mma.sync.aligned.m16n8k16.row.col.f32.bf16.bf16.f32 "
        "{%0,%1,%2,%3}, {%4,%5,%6,%7}, {%8,%9}, {%0,%1,%2,%3};"
        : "+f"(c[0]), "+f"(c[1]), "+f"(c[2]), "+f"(c[3])
        : "r"(a[0]), "r"(a[1]), "r"(a[2]), "r"(a[3]), "r"(b0), "r"(b1));
}

__device__ __forceinline__ void split2(float x, bf16& h, bf16& l) {
    h = __float2bfloat16(x);
    l = __float2bfloat16(x - __bfloat162float(h));
}

// swizzled byte offset inside a (rows x 32) bf16 tile (64B rows)
__device__ __forceinline__ uint32_t swz(int row, int kbyte) {
    return (uint32_t)(row * 64 + (kbyte ^ ((row & 6) << 3)));
}

// ---------------- GEMM: D = A @ B^T, bf16 hi/lo 3-term ----------------
// Tile 128x64x32, 8 warps (warp 32x32), 3-stage cp.async pipeline, 3 CTA/SM.
// MODE 0: epi fp32*alpha
// MODE 3: causal tile-skip (bx*64 > by*128+127) + epi fp32*alpha
// MODE 4: k-limit kEnd=(by+1)*128 + epi bf16 hi/lo
// MODE 5: fused QKV: bx selects {Q,K,V}; V epilogue transposed per-batch
static constexpr int BK = 32;
static constexpr int TILE_A = 128 * BK * 2;          // 8 KB
static constexpr int TILE_Bb = 64 * BK * 2;          // 4 KB
static constexpr int OFF_AH = 0, OFF_AL = TILE_A, OFF_BH = 2*TILE_A, OFF_BL = 2*TILE_A + TILE_Bb;
static constexpr int STAGE_B = 2*TILE_A + 2*TILE_Bb; // 24 KB
static constexpr int STAGES = 3;
static constexpr int SMEM_DYN = STAGES * STAGE_B;    // 72 KB

template <int MODE>
__global__ __launch_bounds__(256, 3)
void gemm_mma(const bf16* __restrict__ Ah, const bf16* __restrict__ Al,
              const bf16* __restrict__ Bh, const bf16* __restrict__ Bl,
              float* __restrict__ Cf, bf16* __restrict__ Ch, bf16* __restrict__ Cl,
              const bf16* __restrict__ Bkh, const bf16* __restrict__ Bkl,
              const bf16* __restrict__ Bvh, const bf16* __restrict__ Bvl,
              bf16* __restrict__ Ckh, bf16* __restrict__ Ckl,
              bf16* __restrict__ Cvh, bf16* __restrict__ Cvl,
              int lda, int ldb, int kmax, int Nc,
              size_t sA, size_t sB, size_t sC, float alpha)
{
    const int bx = blockIdx.x, by = blockIdx.y, bz = blockIdx.z;
    if (MODE == 3 && bx * 64 > by * 128 + 127) return;
    const int m0 = by * 128;
    int n0 = bx * 64;
    if (MODE == 4) kmax = (by + 1) * 128;

    const bf16* pAh = Ah + bz * sA;
    const bf16* pAl = Al + bz * sA;
    const bf16* pBh = Bh + bz * sB;
    const bf16* pBl = Bl + bz * sB;
    bf16* outCh = Ch;
    bf16* outCl = Cl;
    int which = 0;
    if (MODE == 5) {
        which = bx >> 4;
        n0 = (bx & 15) * 64;
        if (which == 1) { pBh = Bkh; pBl = Bkl; outCh = Ckh; outCl = Ckl; }
        else if (which == 2) { pBh = Bvh; pBl = Bvl; outCh = Cvh; outCl = Cvl; }
    }

    extern __shared__ char dsm[];
    const uint32_t sbase = smem_u32(dsm);

    const int tid = threadIdx.x;
    const int wid = tid >> 5, lane = tid & 31;
    const int wm = wid & 3, wn = wid >> 2;       // warp tile: rows wm*32, cols wn*32

    // loader mapping: A gets 2 chunks (rows 0-63, 64-127), B gets 1 chunk (rows 0-63)
    const int r0c = tid >> 2, k0c = (tid & 3) << 4;
    const int r1c = r0c + 64;
    const uint32_t so0 = swz(r0c, k0c), so1 = swz(r1c, k0c);

    // ldmatrix offsets
    const int lr = lane & 15, lc16 = (lane >> 4) << 4;
    uint32_t aoff[2][2], boff[2][2];
    #pragma unroll
    for (int mi = 0; mi < 2; mi++) {
        int row = wm * 32 + mi * 16 + lr;
        #pragma unroll
        for (int ks = 0; ks < 2; ks++) aoff[mi][ks] = swz(row, ks * 32 + lc16);
    }
    #pragma unroll
    for (int nb = 0; nb < 2; nb++) {
        int row = wn * 32 + nb * 16 + lr;
        #pragma unroll
        for (int ks = 0; ks < 2; ks++) boff[nb][ks] = swz(row, ks * 32 + lc16);
    }

    float acc[2][4][4];
    #pragma unroll
    for (int mi = 0; mi < 2; mi++)
        #pragma unroll
        for (int nf = 0; nf < 4; nf++)
            #pragma unroll
            for (int q = 0; q < 4; q++) acc[mi][nf][q] = 0.0f;

    const int nit = kmax / BK;

    auto prefetch = [&](int it, int stage) {
        const int k0 = it * BK + (k0c >> 1);
        const uint32_t sb = sbase + stage * STAGE_B;
        CP16(sb + OFF_AH + so0, pAh + (size_t)(m0 + r0c) * lda + k0);
        CP16(sb + OFF_AH + so1, pAh + (size_t)(m0 + r1c) * lda + k0);
        CP16(sb + OFF_AL + so0, pAl + (size_t)(m0 + r0c) * lda + k0);
        CP16(sb + OFF_AL + so1, pAl + (size_t)(m0 + r1c) * lda + k0);
        CP16(sb + OFF_BH + so0, pBh + (size_t)(n0 + r0c) * ldb + k0);
        CP16(sb + OFF_BL + so0, pBl + (size_t)(n0 + r0c) * ldb + k0);
    };

    prefetch(0, 0); CPCOMMIT();
    if (nit > 1) prefetch(1, 1);
    CPCOMMIT();

    for (int it = 0; it < nit; it++) {
        CPWAIT1();
        __syncthreads();
        if (it + 2 < nit) prefetch(it + 2, (it + 2) % STAGES);
        CPCOMMIT();

        const uint32_t sb = sbase + (it % STAGES) * STAGE_B;
        #pragma unroll
        for (int ks = 0; ks < 2; ks++) {
            uint32_t Afr[2][4], Bt[2][4];
            #pragma unroll
            for (int mi = 0; mi < 2; mi++)
                LDSM4(Afr[mi][0], Afr[mi][1], Afr[mi][2], Afr[mi][3],
                      sb + OFF_AH + aoff[mi][ks]);
            #pragma unroll
            for (int nb = 0; nb < 2; nb++)
                LDSM4(Bt[nb][0], Bt[nb][1], Bt[nb][2], Bt[nb][3],
                      sb + OFF_BH + boff[nb][ks]);
            // hi*hi
            #pragma unroll
            for (int mi = 0; mi < 2; mi++)
                #pragma unroll
                for (int nf = 0; nf < 4; nf++)
                    mma16816(acc[mi][nf], Afr[mi], Bt[nf >> 1][nf & 1], Bt[nf >> 1][(nf & 1) + 2]);
            // lo*hi
            {
                uint32_t Alf[2][4];
                #pragma unroll
                for (int mi = 0; mi < 2; mi++)
                    LDSM4(Alf[mi][0], Alf[mi][1], Alf[mi][2], Alf[mi][3],
                          sb + OFF_AL + aoff[mi][ks]);
                #pragma unroll
                for (int mi = 0; mi < 2; mi++)
                    #pragma unroll
                    for (int nf = 0; nf < 4; nf++)
                        mma16816(acc[mi][nf], Alf[mi], Bt[nf >> 1][nf & 1], Bt[nf >> 1][(nf & 1) + 2]);
            }
            // hi*lo
            #pragma unroll
            for (int nb = 0; nb < 2; nb++)
                LDSM4(Bt[nb][0], Bt[nb][1], Bt[nb][2], Bt[nb][3],
                      sb + OFF_BL + boff[nb][ks]);
            #pragma unroll
            for (int mi = 0; mi < 2; mi++)
                #pragma unroll
                for (int nf = 0; nf < 4; nf++)
                    mma16816(acc[mi][nf], Afr[mi], Bt[nf >> 1][nf & 1], Bt[nf >> 1][(nf & 1) + 2]);
        }
    }

    // ---------------- epilogue ----------------
    const int quad = lane >> 2, tq = lane & 3;
    #pragma unroll
    for (int mi = 0; mi < 2; mi++) {
        #pragma unroll
        for (int h = 0; h < 2; h++) {
            const int r = m0 + wm * 32 + mi * 16 + quad + h * 8;
            if (MODE == 0 || MODE == 3) {
                float* crow = Cf + bz * sC + (size_t)r * Nc + n0 + wn * 32 + tq * 2;
                #pragma unroll
                for (int nf = 0; nf < 4; nf++) {
                    float2 v;
                    v.x = acc[mi][nf][h * 2 + 0] * alpha;
                    v.y = acc[mi][nf][h * 2 + 1] * alpha;
                    *(float2*)(crow + nf * 8) = v;
                }
            } else if (MODE == 4 || (MODE == 5 && which < 2)) {
                bf16* hrow = outCh + bz * sC + (size_t)r * Nc + n0 + wn * 32 + tq * 2;
                bf16* lrow = outCl + bz * sC + (size_t)r * Nc + n0 + wn * 32 + tq * 2;
                #pragma unroll
                for (int nf = 0; nf < 4; nf++) {
                    bf16 h0, l0, h1, l1;
                    split2(acc[mi][nf][h * 2 + 0], h0, l0);
                    split2(acc[mi][nf][h * 2 + 1], h1, l1);
                    __nv_bfloat162 hp; hp.x = h0; hp.y = h1;
                    __nv_bfloat162 lp; lp.x = l0; lp.y = l1;
                    *(__nv_bfloat162*)(hrow + nf * 8) = hp;
                    *(__nv_bfloat162*)(lrow + nf * 8) = lp;
                }
            } else {  // MODE 5, V: transposed Vt[b][c][t]
                const int b = r >> 11, t = r & (TT - 1);
                const size_t base = (size_t)b * CC * TT + t;
                #pragma unroll
                for (int nf = 0; nf < 4; nf++) {
                    const int c0 = n0 + wn * 32 + nf * 8 + tq * 2;
                    bf16 h0, l0, h1, l1;
                    split2(acc[mi][nf][h * 2 + 0], h0, l0);
                    split2(acc[mi][nf][h * 2 + 1], h1, l1);
                    outCh[base + (size_t)c0 * TT] = h0;
                    outCl[base + (size_t)c0 * TT] = l0;
                    outCh[base + (size_t)(c0 + 1) * TT] = h1;
                    outCl[base + (size_t)(c0 + 1) * TT] = l1;
                }
            }
        }
    }
}

// ---------------- fp32 -> bf16 hi/lo split ----------------
__global__ __launch_bounds__(256)
void split_f32(const float* __restrict__ x, bf16* __restrict__ h, bf16* __restrict__ l, int n)
{
    int i = (blockIdx.x * 256 + threadIdx.x) * 4;
    if (i >= n) return;
    float4 v = *(const float4*)(x + i);
    __align__(8) bf16 hh[4], ll[4];
    split2(v.x, hh[0], ll[0]); split2(v.y, hh[1], ll[1]);
    split2(v.z, hh[2], ll[2]); split2(v.w, hh[3], ll[3]);
    *(uint2*)(h + i) = *(uint2*)hh;
    *(uint2*)(l + i) = *(uint2*)ll;
}

// 4 weight matrices: W[k][n] -> Wt hi/lo [n][k], z selects matrix
__global__ __launch_bounds__(256)
void wsplitT4(const float* __restrict__ w0, const float* __restrict__ w1,
              const float* __restrict__ w2, const float* __restrict__ w3,
              bf16* __restrict__ h0, bf16* __restrict__ h1,
              bf16* __restrict__ h2, bf16* __restrict__ h3,
              bf16* __restrict__ l0, bf16* __restrict__ l1,
              bf16* __restrict__ l2, bf16* __restrict__ l3)
{
    const int z = blockIdx.z;
    const float* W = (z == 0) ? w0 : (z == 1) ? w1 : (z == 2) ? w2 : w3;
    bf16* Th = (z == 0) ? h0 : (z == 1) ? h1 : (z == 2) ? h2 : h3;
    bf16* Tl = (z == 0) ? l0 : (z == 1) ? l1 : (z == 2) ? l2 : l3;

    __shared__ float t[32][33];
    const int n0 = blockIdx.x * 32, k0 = blockIdx.y * 32;
    const int tx = threadIdx.x & 31, ty = threadIdx.x >> 5;
    #pragma unroll
    for (int i = 0; i < 4; i++)
        t[ty + 8*i][tx] = W[(size_t)(k0 + ty + 8*i) * CC + n0 + tx];
    __syncthreads();
    #pragma unroll
    for (int i = 0; i < 4; i++) {
        float v = t[tx][ty + 8*i];
        bf16 h, l;
        split2(v, h, l);
        Th[(size_t)(n0 + ty + 8*i) * CC + k0 + tx] = h;
        Tl[(size_t)(n0 + ty + 8*i) * CC + k0 + tx] = l;
    }
}

// ---------------- causal softmax: register-resident single pass ----------------
__global__ __launch_bounds__(256)
void softmax_causal(const float* __restrict__ S, bf16* __restrict__ Ph, bf16* __restrict__ Pl)
{
    const int r = blockIdx.x;
    const int t = r & (TT - 1);
    const float* row = S + (size_t)r * TT;
    bf16* ph = Ph + (size_t)r * TT;
    bf16* pl = Pl + (size_t)r * TT;
    const int len = t + 1;
    const int zmax = ((t >> 7) + 1) << 7;

    const int tid = threadIdx.x, lane = tid & 31, wid = tid >> 5;
    __shared__ float red[32];

    float v[8];
    float m = -3.0e38f;
    #pragma unroll
    for (int i = 0; i < 8; i++) {
        int s = tid + i * 256;
        v[i] = (s < len) ? row[s] : -3.0e38f;
        m = fmaxf(m, v[i]);
    }
    #pragma unroll
    for (int o = 16; o > 0; o >>= 1) m = fmaxf(m, __shfl_xor_sync(0xffffffffu, m, o));
    if (lane == 0) red[wid] = m;
    __syncthreads();
    if (tid < 32) {
        float x = (tid < 8) ? red[tid] : -3.0e38f;
        #pragma unroll
        for (int o = 4; o > 0; o >>= 1) x = fmaxf(x, __shfl_xor_sync(0xffffffffu, x, o));
        if (tid == 0) red[0] = x;
    }
    __syncthreads();
    m = red[0];
    __syncthreads();

    float sum = 0.0f;
    #pragma unroll
    for (int i = 0; i < 8; i++) {
        int s = tid + i * 256;
        if (s < len) { v[i] = expf(v[i] - m); sum += v[i]; }
    }
    #pragma unroll
    for (int o = 16; o > 0; o >>= 1) sum += __shfl_xor_sync(0xffffffffu, sum, o);
    if (lane == 0) red[wid] = sum;
    __syncthreads();
    if (tid < 32) {
        float x = (tid < 8) ? red[tid] : 0.0f;
        #pragma unroll
        for (int o = 4; o > 0; o >>= 1) x += __shfl_xor_sync(0xffffffffu, x, o);
        if (tid == 0) red[0] = x;
    }
    __syncthreads();
    const float inv = 1.0f / red[0];

    const bf16 z = __float2bfloat16(0.0f);
    #pragma unroll
    for (int i = 0; i < 8; i++) {
        int s = tid + i * 256;
        if (s < len) {
            bf16 h, l;
            split2(v[i] * inv, h, l);
            ph[s] = h; pl[s] = l;
        } else if (s < zmax) {
            ph[s] = z; pl[s] = z;
        }
    }
}

// ---------------- launch ----------------
extern "C" void kernel_launch(void* const* d_in, const int* in_sizes, int n_in,
                              void* d_out, int out_size)
{
    const float* X  = (const float*)d_in[0];
    const float* Wq = (const float*)d_in[1];
    const float* Wk = (const float*)d_in[2];
    const float* Wv = (const float*)d_in[3];
    const float* Wo = (const float*)d_in[4];
    float* out = (float*)d_out;

    bf16 *Xh,*Xl,*Wqh,*Wql,*Wkh,*Wkl,*Wvh,*Wvl,*Woh,*Wol;
    bf16 *Qh,*Ql,*Kh,*Kl,*Vth,*Vtl,*Ph,*Pl,*Oh,*Ol;
    float* S;
    cudaGetSymbolAddress((void**)&Xh, g_Xh);   cudaGetSymbolAddress((void**)&Xl, g_Xl);
    cudaGetSymbolAddress((void**)&Wqh, g_Wqh); cudaGetSymbolAddress((void**)&Wql, g_Wql);
    cudaGetSymbolAddress((void**)&Wkh, g_Wkh); cudaGetSymbolAddress((void**)&Wkl, g_Wkl);
    cudaGetSymbolAddress((void**)&Wvh, g_Wvh); cudaGetSymbolAddress((void**)&Wvl, g_Wvl);
    cudaGetSymbolAddress((void**)&Woh, g_Woh); cudaGetSymbolAddress((void**)&Wol, g_Wol);
    cudaGetSymbolAddress((void**)&Qh, g_Qh);   cudaGetSymbolAddress((void**)&Ql, g_Ql);
    cudaGetSymbolAddress((void**)&Kh, g_Kh);   cudaGetSymbolAddress((void**)&Kl, g_Kl);
    cudaGetSymbolAddress((void**)&Vth, g_Vth); cudaGetSymbolAddress((void**)&Vtl, g_Vtl);
    cudaGetSymbolAddress((void**)&Ph, g_Ph);   cudaGetSymbolAddress((void**)&Pl, g_Pl);
    cudaGetSymbolAddress((void**)&Oh, g_Oh);   cudaGetSymbolAddress((void**)&Ol, g_Ol);
    cudaGetSymbolAddress((void**)&S, g_S);

    cudaFuncSetAttribute(gemm_mma<0>, cudaFuncAttributeMaxDynamicSharedMemorySize, SMEM_DYN);
    cudaFuncSetAttribute(gemm_mma<3>, cudaFuncAttributeMaxDynamicSharedMemorySize, SMEM_DYN);
    cudaFuncSetAttribute(gemm_mma<4>, cudaFuncAttributeMaxDynamicSharedMemorySize, SMEM_DYN);
    cudaFuncSetAttribute(gemm_mma<5>, cudaFuncAttributeMaxDynamicSharedMemorySize, SMEM_DYN);

    // 1) input splits
    split_f32<<<MT*CC/1024, 256>>>(X, Xh, Xl, MT*CC);
    // 2) all four weight transposes/splits in one launch
    wsplitT4<<<dim3(32,32,4), 256>>>(Wq, Wk, Wv, Wo,
                                     Wqh, Wkh, Wvh, Woh,
                                     Wql, Wkl, Wvl, Wol);

    // 3) fused QKV projections (bx: 0-15 Q, 16-31 K, 32-47 V-transposed)
    gemm_mma<5><<<dim3(48,64,1), 256, SMEM_DYN>>>(Xh, Xl, Wqh, Wql, nullptr, Qh, Ql,
                                                  Wkh, Wkl, Wvh, Wvl, Kh, Kl, Vth, Vtl,
                                                  CC, CC, CC, CC, 0, 0, 0, 1.0f);

    // 4) scores: S[b] = (Q @ K^T)/32, causal tile-skip
    gemm_mma<3><<<dim3(32,16,4), 256, SMEM_DYN>>>(Qh, Ql, Kh, Kl, S, nullptr, nullptr,
                                                  nullptr,nullptr,nullptr,nullptr,
                                                  nullptr,nullptr,nullptr,nullptr,
                                                  CC, CC, CC, TT,
                                                  (size_t)TT*CC, (size_t)TT*CC, (size_t)TT*TT,
                                                  1.0f/32.0f);

    // 5) softmax -> P hi/lo
    softmax_causal<<<BB*TT, 256>>>(S, Ph, Pl);

    // 6) O = P @ Vt^T (k-limited)   [profiled launch]
    gemm_mma<4><<<dim3(16,16,4), 256, SMEM_DYN>>>(Ph, Pl, Vth, Vtl, nullptr, Oh, Ol,
                                                  nullptr,nullptr,nullptr,nullptr,
                                                  nullptr,nullptr,nullptr,nullptr,
                                                  TT, TT, TT, CC,
                                                  (size_t)TT*TT, (size_t)CC*TT, (size_t)TT*CC,
                                                  1.0f);

    // 7) out = O @ Wo^T
    gemm_mma<0><<<dim3(16,64,1), 256, SMEM_DYN>>>(Oh, Ol, Woh, Wol, out, nullptr, nullptr,
                                                  nullptr,nullptr,nullptr,nullptr,
                                                  nullptr,nullptr,nullptr,nullptr,
                                                  CC, CC, CC, CC, 0, 0, 0, 1.0f);
}